// round 10
// baseline (speedup 1.0000x reference)
#include <cuda_runtime.h>

#define NT   256
#define SPB  2
#define NP   20
#define LD   52     // hT/efT leading dim; rows in 4 groups of 10 at 12-slot stride
#define LDE  132    // padded row-major ef/t leading dim (bank-decorrelated, float4-aligned)

typedef unsigned long long u64t;

__device__ __forceinline__ u64t ffma2(u64t a, u64t b, u64t c) {
    u64t d;
    asm("fma.rn.f32x2 %0, %1, %2, %3;" : "=l"(d) : "l"(a), "l"(b), "l"(c));
    return d;
}
__device__ __forceinline__ u64t add2(u64t a, u64t b) {
    u64t d;
    asm("add.rn.f32x2 %0, %1, %2;" : "=l"(d) : "l"(a), "l"(b));
    return d;
}
__device__ __forceinline__ u64t dup2(float x) {
    u64t d;
    asm("mov.b64 %0, {%1, %1};" : "=l"(d) : "f"(x));
    return d;
}
__device__ __forceinline__ float2 unpk(u64t a) {
    float2 r;
    asm("mov.b64 {%0, %1}, %2;" : "=f"(r.x), "=f"(r.y) : "l"(a));
    return r;
}

// ---- batch-invariant folded attention tables (computed per launch by setup_kernel)
__device__ float g_G[128 * 128];   // (Wq @ Wk^T) / sqrt(128)
__device__ float g_u[128];         // (Wq @ bk) / sqrt(128)
__device__ float g_w[128];         // (Wk @ bq) / sqrt(128)
__device__ float g_c;              // (bq . bk) / sqrt(128)

__global__ void setup_kernel(const float* __restrict__ Wq, const float* __restrict__ Wk,
                             const float* __restrict__ bq, const float* __restrict__ bk)
{
    __shared__ float qa[128];
    const int a = blockIdx.x, t = threadIdx.x;
    qa[t] = Wq[a * 128 + t];
    __syncthreads();
    const float scl = 0.088388347648318447f;  // 1/sqrt(128)
    const float* kb = Wk + t * 128;
    float acc = 0.f;
    #pragma unroll 8
    for (int d = 0; d < 128; d++) acc = fmaf(qa[d], kb[d], acc);
    g_G[a * 128 + t] = acc * scl;
    if (t == 0) {
        float u = 0.f;
        for (int d = 0; d < 128; d++) u = fmaf(qa[d], bk[d], u);
        g_u[a] = u * scl;
    }
    if (a == 0) {
        float w = 0.f;
        for (int d = 0; d < 128; d++) w = fmaf(kb[d], bq[d], w);
        g_w[t] = w * scl;
        if (t == 0) {
            float c = 0.f;
            for (int d = 0; d < 128; d++) c = fmaf(bq[d], bk[d], c);
            g_c = c * scl;
        }
    }
}

// smem float offsets
#define OFF_INP   0        // 800  (40 x 20)      [overlay: hr 512]
#define OFF_HT    800      // 1664 (32 x 52)      [overlay: sc 800, colw 48, ab 80, z 256, pool 256]
#define OFF_EFT   2464     // 6656 (128 x 52) transposed ef
#define OFF_EF    9120     // 5280 (40 x 132) row-major ef (padded)
#define OFF_T     14400    // 5280 (40 x 132) row-major t = ef @ G (padded)
#define OFF_WBUF  19680    // 8192
#define OFF_OBS   27872    // 176
#define OFF_DG    28048    // 64
#define OFF_INT   28112    // 100 ints
#define SMEM_ELEMS 28112
// overlays
#define OFF_SC    OFF_HT
#define OFF_COLW  (OFF_HT + 800)
#define OFF_AB    (OFF_HT + 848)    // 80: alpha[40], beta[40]
#define OFF_Z     (OFF_HT + 928)    // 256
#define OFF_POOL  (OFF_HT + 1184)   // 256  (ends at 1440 <= 1664)
#define OFF_HR    0

__global__ __launch_bounds__(NT, 2)
void actor_kernel(
    const float* __restrict__ obs, const float* __restrict__ ag, const float* __restrict__ g,
    const float* __restrict__ W1, const float* __restrict__ b1,
    const float* __restrict__ W2, const float* __restrict__ b2,
    const float* __restrict__ Wv, const float* __restrict__ bv,
    const float* __restrict__ Wr, const float* __restrict__ br,
    const float* __restrict__ Wm, const float* __restrict__ bm,
    const float* __restrict__ Ws, const float* __restrict__ bs,
    const int* __restrict__ edges, const int* __restrict__ pred_ids,
    float* __restrict__ out, int B)
{
    extern __shared__ float sm[];
    float* s_inp  = sm + OFF_INP;
    float* s_hT   = sm + OFF_HT;
    float* s_efT  = sm + OFF_EFT;
    float* s_ef   = sm + OFF_EF;
    float* s_t    = sm + OFF_T;
    float* s_wbuf = sm + OFF_WBUF;
    float* s_obs  = sm + OFF_OBS;
    float* s_dg   = sm + OFF_DG;
    float* s_sc   = sm + OFF_SC;
    float* s_colw = sm + OFF_COLW;
    float* s_ab   = sm + OFF_AB;
    float* s_z    = sm + OFF_Z;
    float* s_pool = sm + OFF_POOL;
    float* s_hr   = sm + OFF_HR;
    int*   s_edge = (int*)(sm + OFF_INT);
    int*   s_pred = s_edge + 40;

    const int tid = threadIdx.x;
    const int b0  = blockIdx.x * SPB;

    // ---------- Stage 0: inputs ----------
    for (int i = tid; i < SPB*85; i += NT) {
        int s = i / 85, c = i - 85*s;
        s_obs[s*88 + c] = obs[(size_t)(b0+s)*85 + c];
    }
    for (int i = tid; i < SPB*30; i += NT) {
        int s = i / 30, c = i - 30*s;
        s_dg[s*32 + c] = g[(size_t)(b0+s)*30 + c] - ag[(size_t)(b0+s)*30 + c];
    }
    if (tid < 40) s_edge[tid] = edges[tid];
    if (tid < 60) s_pred[tid] = pred_ids[tid];
    __syncthreads();

    for (int i = tid; i < SPB*NP*19; i += NT) {
        int s = i / (NP*19); int rem = i - s*NP*19;
        int p = rem / 19;    int c = rem - 19*p;
        float val;
        if (c < 10)      val = s_obs[s*88 + c];
        else if (c < 13) val = s_dg[s*32 + s_pred[p*3 + (c-10)]];
        else if (c < 16) val = s_obs[s*88 + 10 + s_edge[p*2]   * 15 + (c-13)];
        else             val = s_obs[s*88 + 10 + s_edge[p*2+1] * 15 + (c-16)];
        s_inp[(s*NP + p)*20 + c] = val;
    }
    for (int i = tid; i < SPB*NP; i += NT) s_inp[i*20 + 19] = 0.f;
    __syncthreads();

    // main GEMM thread mapping
    const int lane = tid & 31;
    const int wrp  = tid >> 5;
    const int ks   = lane & 1;                       // k-interleave bit
    const int cg   = ((wrp & 1) << 4) | (lane >> 1); // 0..31 -> cols 4cg..4cg+3
    const int rg   = wrp >> 1;                       // 0..3 -> rows 10rg..+9 (slots rg*12..)

#define FF5(ACC, HA, HB, HC)                                             \
    ACC[0][0]=ffma2(HA.x,w0,ACC[0][0]); ACC[0][1]=ffma2(HA.x,w1d,ACC[0][1]); \
    ACC[0][2]=ffma2(HA.x,w2d,ACC[0][2]); ACC[0][3]=ffma2(HA.x,w3d,ACC[0][3]); \
    ACC[1][0]=ffma2(HA.y,w0,ACC[1][0]); ACC[1][1]=ffma2(HA.y,w1d,ACC[1][1]); \
    ACC[1][2]=ffma2(HA.y,w2d,ACC[1][2]); ACC[1][3]=ffma2(HA.y,w3d,ACC[1][3]); \
    ACC[2][0]=ffma2(HB.x,w0,ACC[2][0]); ACC[2][1]=ffma2(HB.x,w1d,ACC[2][1]); \
    ACC[2][2]=ffma2(HB.x,w2d,ACC[2][2]); ACC[2][3]=ffma2(HB.x,w3d,ACC[2][3]); \
    ACC[3][0]=ffma2(HB.y,w0,ACC[3][0]); ACC[3][1]=ffma2(HB.y,w1d,ACC[3][1]); \
    ACC[3][2]=ffma2(HB.y,w2d,ACC[3][2]); ACC[3][3]=ffma2(HB.y,w3d,ACC[3][3]); \
    ACC[4][0]=ffma2(HC,w0,ACC[4][0]);   ACC[4][1]=ffma2(HC,w1d,ACC[4][1]);   \
    ACC[4][2]=ffma2(HC,w2d,ACC[4][2]);  ACC[4][3]=ffma2(HC,w3d,ACC[4][3]);

    // ---------- Stage 1+2 fused: ef = relu(relu(inp@W1+b1) @ W2 + b2) ----------
    {
        u64t acc[5][4];
        #pragma unroll
        for (int j = 0; j < 5; j++)
            #pragma unroll
            for (int c = 0; c < 4; c++) acc[j][c] = 0ull;

        for (int cc = 0; cc < 8; cc++) {
            // stage1: build hT for 32 k-columns of this chunk
            {
                int hc = tid & 31, g8 = tid >> 5;
                int hcol = cc*32 + hc;
                float w1r[19];
                #pragma unroll
                for (int c = 0; c < 19; c++) w1r[c] = W1[c*256 + hcol];
                float bb = b1[hcol];
                int slotbase = (g8 >> 1)*12 + 5*(g8 & 1);
                #pragma unroll
                for (int r = 0; r < 5; r++) {
                    int row = g8*5 + r;
                    const float4* ip = (const float4*)(s_inp + row*20);
                    float4 i0 = ip[0], i1 = ip[1], i2 = ip[2], i3 = ip[3], i4 = ip[4];
                    float a = bb;
                    a = fmaf(i0.x, w1r[0], a);  a = fmaf(i0.y, w1r[1], a);
                    a = fmaf(i0.z, w1r[2], a);  a = fmaf(i0.w, w1r[3], a);
                    a = fmaf(i1.x, w1r[4], a);  a = fmaf(i1.y, w1r[5], a);
                    a = fmaf(i1.z, w1r[6], a);  a = fmaf(i1.w, w1r[7], a);
                    a = fmaf(i2.x, w1r[8], a);  a = fmaf(i2.y, w1r[9], a);
                    a = fmaf(i2.z, w1r[10], a); a = fmaf(i2.w, w1r[11], a);
                    a = fmaf(i3.x, w1r[12], a); a = fmaf(i3.y, w1r[13], a);
                    a = fmaf(i3.z, w1r[14], a); a = fmaf(i3.w, w1r[15], a);
                    a = fmaf(i4.x, w1r[16], a); a = fmaf(i4.y, w1r[17], a);
                    a = fmaf(i4.z, w1r[18], a);
                    s_hT[hc*LD + slotbase + r] = fmaxf(a, 0.f);
                }
            }
            // stage W2 chunk (32 x 128)
            {
                const float4* src = (const float4*)(W2 + cc*4096);
                float4* dst = (float4*)s_wbuf;
                dst[tid] = src[tid];
                dst[tid + 256] = src[tid + 256];
                dst[tid + 512] = src[tid + 512];
                dst[tid + 768] = src[tid + 768];
            }
            __syncthreads();
            #pragma unroll 4
            for (int kk = 0; kk < 16; kk++) {
                int k2 = 2*kk + ks;
                const float* hb = s_hT + k2*LD + rg*12;
                ulonglong2 hA = *(const ulonglong2*)hb;
                ulonglong2 hB = *(const ulonglong2*)(hb + 4);
                u64t hC = *(const u64t*)(hb + 8);
                float4 wv = *(const float4*)(s_wbuf + k2*128 + 4*cg);
                u64t w0 = dup2(wv.x), w1d = dup2(wv.y), w2d = dup2(wv.z), w3d = dup2(wv.w);
                FF5(acc, hA, hB, hC)
            }
            __syncthreads();
        }
        // k-split reduce across lane pairs
        #pragma unroll
        for (int j = 0; j < 5; j++)
            #pragma unroll
            for (int c = 0; c < 4; c++) {
                u64t o = __shfl_xor_sync(0xffffffffu, acc[j][c], 1);
                acc[j][c] = add2(acc[j][c], o);
            }
        // epilogue: bias + relu; store transposed (for GEMM) AND row-major padded (for scores/z)
        if (ks == 0) {
            float4 bb = *(const float4*)(b2 + 4*cg);
            float barr[4] = {bb.x, bb.y, bb.z, bb.w};
            #pragma unroll
            for (int c = 0; c < 4; c++)
                #pragma unroll
                for (int j = 0; j < 5; j++) {
                    float2 e = unpk(acc[j][c]);
                    e.x = fmaxf(e.x + barr[c], 0.f);
                    e.y = fmaxf(e.y + barr[c], 0.f);
                    *(float2*)(s_efT + (4*cg + c)*LD + rg*12 + 2*j) = e;
                    int row = rg*10 + 2*j;
                    s_ef[ row     *LDE + 4*cg + c] = e.x;
                    s_ef[(row + 1)*LDE + 4*cg + c] = e.y;
                }
        }
    }

    // ---------- Stage 3: t = ef @ G (Q,K folded; scale pre-applied in G) ----------
    {
        u64t acc[5][4];
        #pragma unroll
        for (int j = 0; j < 5; j++)
            #pragma unroll
            for (int c = 0; c < 4; c++) acc[j][c] = 0ull;

        for (int cc = 0; cc < 2; cc++) {
            {
                const float4* src = (const float4*)(g_G + cc*8192);
                float4* dst = (float4*)s_wbuf;
                #pragma unroll
                for (int i = 0; i < 8; i++) dst[tid + i*256] = src[tid + i*256];
            }
            __syncthreads();
            #pragma unroll 4
            for (int kk = 0; kk < 32; kk++) {
                int k2 = 2*kk + ks;
                const float* eb = s_efT + (cc*64 + k2)*LD + rg*12;
                ulonglong2 hA = *(const ulonglong2*)eb;
                ulonglong2 hB = *(const ulonglong2*)(eb + 4);
                u64t hC = *(const u64t*)(eb + 8);
                float4 wv = *(const float4*)(s_wbuf + k2*128 + 4*cg);
                u64t w0 = dup2(wv.x), w1d = dup2(wv.y), w2d = dup2(wv.z), w3d = dup2(wv.w);
                FF5(acc, hA, hB, hC)
            }
            __syncthreads();
        }
        #pragma unroll
        for (int j = 0; j < 5; j++)
            #pragma unroll
            for (int c = 0; c < 4; c++) {
                u64t o = __shfl_xor_sync(0xffffffffu, acc[j][c], 1);
                acc[j][c] = add2(acc[j][c], o);
            }
        if (ks == 0) {
            #pragma unroll
            for (int c = 0; c < 4; c++)
                #pragma unroll
                for (int j = 0; j < 5; j++) {
                    float2 e = unpk(acc[j][c]);
                    int row = rg*10 + 2*j;
                    s_t[ row     *LDE + 4*cg + c] = e.x;
                    s_t[(row + 1)*LDE + 4*cg + c] = e.y;
                }
        }
    }
    __syncthreads();

    // ---------- Stage 4a: alpha/beta rank-1 terms ----------
    if (tid < 80) {
        int row = tid >> 1, sel = tid & 1;   // global row 0..39
        const float4* vec = (const float4*)(sel ? g_w : g_u);
        const float4* er  = (const float4*)(s_ef + row*LDE);
        float a = 0.f;
        #pragma unroll 8
        for (int i = 0; i < 32; i++) {
            float4 e = er[i], v = vec[i];
            a = fmaf(e.x, v.x, a); a = fmaf(e.y, v.y, a);
            a = fmaf(e.z, v.z, a); a = fmaf(e.w, v.w, a);
        }
        s_ab[sel*40 + row] = a;
    }
    __syncthreads();

    // ---------- Stage 4b: scores = t @ ef^T + alpha_p + beta_r + c ----------
    if (tid < 200) {
        int s  = tid / 100, t2 = tid % 100;
        int p0 = (t2 / 10) * 2, r0 = (t2 % 10) * 2;
        const u64t* qA = (const u64t*)(s_t  + (s*20 + p0)*LDE);
        const u64t* qB = (const u64t*)(s_t  + (s*20 + p0 + 1)*LDE);
        const u64t* kA = (const u64t*)(s_ef + (s*20 + r0)*LDE);
        const u64t* kB = (const u64t*)(s_ef + (s*20 + r0 + 1)*LDE);
        u64t a00 = 0ull, a01 = 0ull, a10 = 0ull, a11 = 0ull;
        #pragma unroll 8
        for (int i = 0; i < 64; i++) {
            u64t q0 = qA[i], q1 = qB[i], k0 = kA[i], k1 = kB[i];
            a00 = ffma2(q0, k0, a00); a01 = ffma2(q0, k1, a01);
            a10 = ffma2(q1, k0, a10); a11 = ffma2(q1, k1, a11);
        }
        float cc = g_c;
        float al0 = s_ab[s*20 + p0] + cc, al1 = s_ab[s*20 + p0 + 1] + cc;
        float be0 = s_ab[40 + s*20 + r0], be1 = s_ab[40 + s*20 + r0 + 1];
        float2 f;
        f = unpk(a00); s_sc[(s*20 + p0    )*NP + r0    ] = f.x + f.y + al0 + be0;
        f = unpk(a01); s_sc[(s*20 + p0    )*NP + r0 + 1] = f.x + f.y + al0 + be1;
        f = unpk(a10); s_sc[(s*20 + p0 + 1)*NP + r0    ] = f.x + f.y + al1 + be0;
        f = unpk(a11); s_sc[(s*20 + p0 + 1)*NP + r0 + 1] = f.x + f.y + al1 + be1;
    }
    __syncthreads();

    // ---------- Stage 5: softmax + column sums ----------
    if (tid < SPB*NP) {
        float* row = &s_sc[tid*NP];
        float mx = row[0];
        #pragma unroll
        for (int r = 1; r < NP; r++) mx = fmaxf(mx, row[r]);
        float sum = 0.f;
        #pragma unroll
        for (int r = 0; r < NP; r++) { float e = __expf(row[r] - mx); row[r] = e; sum += e; }
        float inv = 1.f / sum;
        #pragma unroll
        for (int r = 0; r < NP; r++) row[r] *= inv;
    }
    __syncthreads();
    if (tid < SPB*NP) {
        int s = tid / NP, r = tid - NP*s;
        float a = 0.f;
        #pragma unroll
        for (int p = 0; p < NP; p++) a += s_sc[(s*NP + p)*NP + r];
        s_colw[tid] = a;
    }
    __syncthreads();

    // ---------- Stage 6: z = colw @ ef ----------
    {
        int s = tid >> 7, d = tid & 127;
        float a = 0.f;
        #pragma unroll
        for (int r = 0; r < NP; r++) a = fmaf(s_colw[s*NP + r], s_ef[(s*NP + r)*LDE + d], a);
        s_z[s*128 + d] = a;
    }
    __syncthreads();

    // ---------- Stage 6b: pooled = z @ Wv + 20*bv ----------
    {
        int s = tid >> 7, d = tid & 127;
        float a = 20.f * bv[d];
        #pragma unroll 8
        for (int k = 0; k < 128; k++) a = fmaf(s_z[s*128 + k], Wv[k*128 + d], a);
        s_pool[s*128 + d] = a;
    }
    __syncthreads();

    // ---------- Stage 7: hr = relu(pooled @ Wr + br) ----------
    {
        float a0 = br[tid], a1 = a0;
        #pragma unroll 8
        for (int d = 0; d < 128; d++) {
            float w = Wr[d*256 + tid];
            a0 = fmaf(s_pool[d],       w, a0);
            a1 = fmaf(s_pool[128 + d], w, a1);
        }
        s_hr[tid]       = fmaxf(a0, 0.f);
        s_hr[256 + tid] = fmaxf(a1, 0.f);
    }
    __syncthreads();

    // ---------- Stage 8: heads ----------
    {
        int w = tid >> 5, ln = tid & 31;
        for (int o = w; o < 16; o += 8) {
            int s = o >> 3, head = (o >> 2) & 1, a = o & 3;
            const float* Wh = head ? Ws : Wm;
            float acc8 = 0.f;
            #pragma unroll
            for (int j = ln; j < 256; j += 32)
                acc8 = fmaf(s_hr[s*256 + j], Wh[j*4 + a], acc8);
            #pragma unroll
            for (int off = 16; off > 0; off >>= 1)
                acc8 += __shfl_xor_sync(0xffffffffu, acc8, off);
            if (ln == 0) {
                float val = acc8 + (head ? bs[a] : bm[a]);
                size_t bg = (size_t)(b0 + s);
                if (head) {
                    val = fminf(fmaxf(val, -20.f), 2.f);
                    out[(size_t)B*4 + bg*4 + a] = val;
                } else {
                    out[bg*4 + a] = val;
                }
            }
        }
    }
}

extern "C" void kernel_launch(void* const* d_in, const int* in_sizes, int n_in,
                              void* d_out, int out_size) {
    const float* obs = (const float*)d_in[0];
    const float* ag  = (const float*)d_in[1];
    const float* g   = (const float*)d_in[2];
    const float* W1  = (const float*)d_in[3];
    const float* b1  = (const float*)d_in[4];
    const float* W2  = (const float*)d_in[5];
    const float* b2  = (const float*)d_in[6];
    const float* Wq  = (const float*)d_in[7];
    const float* bq  = (const float*)d_in[8];
    const float* Wk  = (const float*)d_in[9];
    const float* bk  = (const float*)d_in[10];
    const float* Wv  = (const float*)d_in[11];
    const float* bv  = (const float*)d_in[12];
    const float* Wr  = (const float*)d_in[13];
    const float* br  = (const float*)d_in[14];
    const float* Wm  = (const float*)d_in[15];
    const float* bm  = (const float*)d_in[16];
    const float* Ws  = (const float*)d_in[17];
    const float* bs  = (const float*)d_in[18];
    const int* edges    = (const int*)d_in[19];
    const int* pred_ids = (const int*)d_in[20];
    float* out = (float*)d_out;

    const int B = in_sizes[0] / 85;

    // fold Wq/Wk/bq/bk into G/u/w/c (batch-invariant)
    setup_kernel<<<128, 128>>>(Wq, Wk, bq, bk);

    const size_t smem = (size_t)(SMEM_ELEMS + 100) * 4;  // 112,848 B -> 2 blocks/SM
    cudaFuncSetAttribute(actor_kernel, cudaFuncAttributeMaxDynamicSharedMemorySize, (int)smem);

    actor_kernel<<<B / SPB, NT, smem>>>(
        obs, ag, g, W1, b1, W2, b2, Wv, bv,
        Wr, br, Wm, bm, Ws, bs, edges, pred_ids, out, B);
}

// round 11
// speedup vs baseline: 1.0213x; 1.0213x over previous
#include <cuda_runtime.h>
#include <cuda_bf16.h>
#include <cstdint>

#define NT   256
#define SPB  2
#define NP   20
#define LDE  132
#define PA   136   // A smem pitch (bf16)
#define PB   72    // B smem pitch (bf16)

typedef unsigned long long u64t;

__device__ __forceinline__ u64t ffma2(u64t a, u64t b, u64t c) {
    u64t d; asm("fma.rn.f32x2 %0, %1, %2, %3;" : "=l"(d) : "l"(a), "l"(b), "l"(c)); return d;
}
__device__ __forceinline__ float2 unpk(u64t a) {
    float2 r; asm("mov.b64 {%0, %1}, %2;" : "=f"(r.x), "=f"(r.y) : "l"(a)); return r;
}
__device__ __forceinline__ uint32_t smem_u32(const void* p) {
    uint32_t a; asm("{ .reg .u64 t; cvta.to.shared.u64 t, %1; cvt.u32.u64 %0, t; }" : "=r"(a) : "l"(p)); return a;
}
#define LDSM4(r0,r1,r2,r3,a) asm volatile("ldmatrix.sync.aligned.m8n8.x4.shared.b16 {%0,%1,%2,%3},[%4];":"=r"(r0),"=r"(r1),"=r"(r2),"=r"(r3):"r"(a))
#define LDSM2(r0,r1,a)       asm volatile("ldmatrix.sync.aligned.m8n8.x2.shared.b16 {%0,%1},[%2];":"=r"(r0),"=r"(r1):"r"(a))
#define MMAB(Cr,A0,A1,A2,A3,B0,B1) asm volatile( \
    "mma.sync.aligned.m16n8k16.row.col.f32.bf16.bf16.f32 {%0,%1,%2,%3},{%4,%5,%6,%7},{%8,%9},{%0,%1,%2,%3};" \
    : "+f"(Cr[0]),"+f"(Cr[1]),"+f"(Cr[2]),"+f"(Cr[3]) \
    : "r"(A0),"r"(A1),"r"(A2),"r"(A3),"r"(B0),"r"(B1))

// ---- batch-invariant folded tables + pre-split weight images
__device__ float g_G[16384], g_u[128], g_w[128], g_c;
__device__ __align__(16) __nv_bfloat16 g_W2s[3][32768]; // [half][cc*8192 + n*64 + kk]
__device__ __align__(16) __nv_bfloat16 g_Gs[3][16384];  // [half][cc*8192 + n*64 + kk]

__global__ void setup_fold(const float* __restrict__ Wq, const float* __restrict__ Wk,
                           const float* __restrict__ bq, const float* __restrict__ bk)
{
    __shared__ float qa[128];
    const int a = blockIdx.x, t = threadIdx.x;
    qa[t] = Wq[a*128 + t];
    __syncthreads();
    const float scl = 0.088388347648318447f;
    const float* kb = Wk + t*128;
    float acc = 0.f;
    #pragma unroll 8
    for (int d = 0; d < 128; d++) acc = fmaf(qa[d], kb[d], acc);
    g_G[a*128 + t] = acc * scl;
    if (t == 0) { float u=0.f; for(int d=0;d<128;d++) u=fmaf(qa[d],bk[d],u); g_u[a]=u*scl; }
    if (a == 0) {
        float w=0.f; for(int d=0;d<128;d++) w=fmaf(kb[d],bq[d],w); g_w[t]=w*scl;
        if (t==0){ float c=0.f; for(int d=0;d<128;d++) c=fmaf(bq[d],bk[d],c); g_c=c*scl; }
    }
}

__global__ void setup_pack(const float* __restrict__ W2) {
    int idx = blockIdx.x*128 + threadIdx.x;   // 32768 threads
    {
        int k = idx >> 7, n = idx & 127;
        float v = W2[k*128 + n];
        int dst = ((k>>6)*128 + n)*64 + (k&63);
        __nv_bfloat16 h = __float2bfloat16(v); float r = v - __bfloat162float(h);
        __nv_bfloat16 m = __float2bfloat16(r); float r2 = r - __bfloat162float(m);
        g_W2s[0][dst]=h; g_W2s[1][dst]=m; g_W2s[2][dst]=__float2bfloat16(r2);
    }
    if (idx < 16384) {
        int k = idx >> 7, n = idx & 127;
        float v = g_G[k*128 + n];
        int dst = ((k>>6)*128 + n)*64 + (k&63);
        __nv_bfloat16 h = __float2bfloat16(v); float r = v - __bfloat162float(h);
        __nv_bfloat16 m = __float2bfloat16(r); float r2 = r - __bfloat162float(m);
        g_Gs[0][dst]=h; g_Gs[1][dst]=m; g_Gs[2][dst]=__float2bfloat16(r2);
    }
}

// smem float offsets
#define OFF_INP  0        // 800  [overlay: hr 512]
#define OFF_EF   800      // 5280 (40 x 132)
#define OFF_T    6080     // 5280
#define OFF_A    11360    // 3*3264 floats = 3 bf16 halves of A[48][136]
#define OFF_B    21152    // 4608 floats = B[128][72] bf16   [overlay: sc/colw/ab/z/pool]
#define OFF_OBS  25760    // 176
#define OFF_DG   25936    // 64
#define OFF_INT  26000    // 100 ints
#define SMEM_ELEMS 26100
#define OFF_SC   OFF_B
#define OFF_COLW (OFF_B + 800)
#define OFF_AB   (OFF_B + 848)
#define OFF_Z    (OFF_B + 928)
#define OFF_POOL (OFF_B + 1184)
#define OFF_HR   0

__global__ __launch_bounds__(NT, 2)
void actor_kernel(
    const float* __restrict__ obs, const float* __restrict__ ag, const float* __restrict__ g,
    const float* __restrict__ W1, const float* __restrict__ b1, const float* __restrict__ b2,
    const float* __restrict__ Wv, const float* __restrict__ bv,
    const float* __restrict__ Wr, const float* __restrict__ br,
    const float* __restrict__ Wm, const float* __restrict__ bm,
    const float* __restrict__ Ws, const float* __restrict__ bs,
    const int* __restrict__ edges, const int* __restrict__ pred_ids,
    float* __restrict__ out, int B)
{
    extern __shared__ float sm[];
    float* s_inp  = sm + OFF_INP;
    float* s_ef   = sm + OFF_EF;
    float* s_t    = sm + OFF_T;
    __nv_bfloat16* s_Abf = (__nv_bfloat16*)(sm + OFF_A);   // halves at +0, +6528, +13056 (bf16 elems)
    __nv_bfloat16* s_Bbf = (__nv_bfloat16*)(sm + OFF_B);
    float* s_obs  = sm + OFF_OBS;
    float* s_dg   = sm + OFF_DG;
    float* s_sc   = sm + OFF_SC;
    float* s_colw = sm + OFF_COLW;
    float* s_ab   = sm + OFF_AB;
    float* s_z    = sm + OFF_Z;
    float* s_pool = sm + OFF_POOL;
    float* s_hr   = sm + OFF_HR;
    int*   s_edge = (int*)(sm + OFF_INT);
    int*   s_pred = s_edge + 40;

    const int tid = threadIdx.x;
    const int b0  = blockIdx.x * SPB;

    // ---------- Stage 0: inputs ----------
    for (int i = tid; i < SPB*85; i += NT) {
        int s = i/85, c = i-85*s;
        s_obs[s*88+c] = obs[(size_t)(b0+s)*85 + c];
    }
    for (int i = tid; i < SPB*30; i += NT) {
        int s = i/30, c = i-30*s;
        s_dg[s*32+c] = g[(size_t)(b0+s)*30 + c] - ag[(size_t)(b0+s)*30 + c];
    }
    if (tid < 40) s_edge[tid] = edges[tid];
    if (tid < 60) s_pred[tid] = pred_ids[tid];
    // zero A pad rows 40..47 (all 3 halves)
    for (int i = tid; i < 3*8*PA; i += NT) {
        int h = i/(8*PA), rem = i%(8*PA);
        s_Abf[h*6528 + (40 + rem/PA)*PA + rem%PA] = __float2bfloat16(0.f);
    }
    __syncthreads();
    for (int i = tid; i < SPB*NP*19; i += NT) {
        int s = i/(NP*19); int rem = i - s*NP*19;
        int p = rem/19;    int c = rem - 19*p;
        float val;
        if (c < 10)      val = s_obs[s*88 + c];
        else if (c < 13) val = s_dg[s*32 + s_pred[p*3 + (c-10)]];
        else if (c < 16) val = s_obs[s*88 + 10 + s_edge[p*2]   * 15 + (c-13)];
        else             val = s_obs[s*88 + 10 + s_edge[p*2+1] * 15 + (c-16)];
        s_inp[(s*NP + p)*20 + c] = val;
    }
    for (int i = tid; i < SPB*NP; i += NT) s_inp[i*20 + 19] = 0.f;
    __syncthreads();

    // ---------- mma thread mapping ----------
    const int lane = tid & 31, wrp = tid >> 5;
    const int gid = lane >> 2, tq = lane & 3;
    const int arow  = (lane & 7) + 8*((lane >> 3) & 1);
    const int acolh = 8*(lane >> 4);
    const uint32_t aBase = smem_u32(s_Abf);
    const uint32_t bAddr0 = smem_u32(s_Bbf) + (uint32_t)(((wrp*16 + (lane & 7))*PB + 8*((lane >> 3) & 1))*2);

    float C[3][2][4];
    #pragma unroll
    for (int mt=0; mt<3; mt++) { C[mt][0][0]=C[mt][0][1]=C[mt][0][2]=C[mt][0][3]=0.f;
                                 C[mt][1][0]=C[mt][1][1]=C[mt][1][2]=C[mt][1][3]=0.f; }

    auto loadB = [&](const __nv_bfloat16* src) {
        const float4* sp = (const float4*)src;
        #pragma unroll
        for (int j=0; j<4; j++) {
            int i = tid + j*256; int row = i>>3, seg = i&7;
            *(float4*)(s_Bbf + row*PB + seg*8) = sp[i];
        }
    };
    auto mma_pass = [&](int half, int kof) {
        uint32_t ab = aBase + half*13056u;
        #pragma unroll
        for (int ks2=0; ks2<4; ks2++) {
            int k0 = ks2*16;
            uint32_t b0a,b1a,b0b,b1b;
            LDSM2(b0a,b1a, bAddr0 + (uint32_t)(k0*2));
            LDSM2(b0b,b1b, bAddr0 + (uint32_t)((8*PB + k0)*2));
            #pragma unroll
            for (int mt=0; mt<3; mt++) {
                uint32_t aad = ab + (uint32_t)(((mt*16 + arow)*PA + kof + k0 + acolh)*2);
                uint32_t a0,a1,a2,a3; LDSM4(a0,a1,a2,a3,aad);
                MMAB(C[mt][0],a0,a1,a2,a3,b0a,b1a);
                MMAB(C[mt][1],a0,a1,a2,a3,b0b,b1b);
            }
        }
    };

    // ---------- Stage 1+2: ef = relu(relu(inp@W1+b1)@W2+b2) via 6-pass split mma ----------
    for (int cc = 0; cc < 4; cc++) {
        {   // stage1: h chunk [40 rows][64 cols] -> split3 into A halves
            int hc = tid & 63, g4 = tid >> 6;
            int hcol = cc*64 + hc;
            float w1r[19];
            #pragma unroll
            for (int c=0;c<19;c++) w1r[c] = W1[c*256 + hcol];
            float bb = b1[hcol];
            #pragma unroll
            for (int r=0;r<10;r++) {
                int row = g4*10 + r;
                const float4* ip = (const float4*)(s_inp + row*20);
                float4 i0=ip[0], i1=ip[1], i2=ip[2], i3=ip[3], i4=ip[4];
                float a = bb;
                a=fmaf(i0.x,w1r[0],a);  a=fmaf(i0.y,w1r[1],a);  a=fmaf(i0.z,w1r[2],a);  a=fmaf(i0.w,w1r[3],a);
                a=fmaf(i1.x,w1r[4],a);  a=fmaf(i1.y,w1r[5],a);  a=fmaf(i1.z,w1r[6],a);  a=fmaf(i1.w,w1r[7],a);
                a=fmaf(i2.x,w1r[8],a);  a=fmaf(i2.y,w1r[9],a);  a=fmaf(i2.z,w1r[10],a); a=fmaf(i2.w,w1r[11],a);
                a=fmaf(i3.x,w1r[12],a); a=fmaf(i3.y,w1r[13],a); a=fmaf(i3.z,w1r[14],a); a=fmaf(i3.w,w1r[15],a);
                a=fmaf(i4.x,w1r[16],a); a=fmaf(i4.y,w1r[17],a); a=fmaf(i4.z,w1r[18],a);
                a = fmaxf(a, 0.f);
                __nv_bfloat16 h = __float2bfloat16(a); float r1 = a - __bfloat162float(h);
                __nv_bfloat16 m = __float2bfloat16(r1); float r2 = r1 - __bfloat162float(m);
                int o = row*PA + hc;
                s_Abf[o] = h; s_Abf[6528+o] = m; s_Abf[13056+o] = __float2bfloat16(r2);
            }
        }
        loadB(g_W2s[0] + cc*8192); __syncthreads();
        mma_pass(0,0); mma_pass(1,0); mma_pass(2,0); __syncthreads();
        loadB(g_W2s[1] + cc*8192); __syncthreads();
        mma_pass(0,0); mma_pass(1,0); __syncthreads();
        loadB(g_W2s[2] + cc*8192); __syncthreads();
        mma_pass(0,0); __syncthreads();
    }
    // epilogue: bias+relu -> s_ef fp32 + split3 -> A halves (rows<40)
    #pragma unroll
    for (int mt=0; mt<3; mt++) {
        int r0 = mt*16 + gid, r1 = r0 + 8;
        #pragma unroll
        for (int nt=0; nt<2; nt++) {
            int n0 = wrp*16 + nt*8 + 2*tq;
            float bb0 = b2[n0], bb1 = b2[n0+1];
            float v[4] = { fmaxf(C[mt][nt][0]+bb0,0.f), fmaxf(C[mt][nt][1]+bb1,0.f),
                           fmaxf(C[mt][nt][2]+bb0,0.f), fmaxf(C[mt][nt][3]+bb1,0.f) };
            int rr[2] = { r0, r1 };
            #pragma unroll
            for (int q=0; q<4; q++) {
                int row = rr[q>>1], col = n0 + (q&1);
                if (row < 40) {
                    float a = v[q];
                    s_ef[row*LDE + col] = a;
                    __nv_bfloat16 h = __float2bfloat16(a); float r1f = a - __bfloat162float(h);
                    __nv_bfloat16 m = __float2bfloat16(r1f); float r2f = r1f - __bfloat162float(m);
                    int o = row*PA + col;
                    s_Abf[o] = h; s_Abf[6528+o] = m; s_Abf[13056+o] = __float2bfloat16(r2f);
                }
            }
            C[mt][nt][0]=C[mt][nt][1]=C[mt][nt][2]=C[mt][nt][3]=0.f;  // re-zero for stage3
        }
    }
    __syncthreads();

    // ---------- Stage 3: t = ef @ G via 6-pass split mma ----------
    for (int c2 = 0; c2 < 2; c2++) {
        loadB(g_Gs[0] + c2*8192); __syncthreads();
        mma_pass(0,c2*64); mma_pass(1,c2*64); mma_pass(2,c2*64); __syncthreads();
        loadB(g_Gs[1] + c2*8192); __syncthreads();
        mma_pass(0,c2*64); mma_pass(1,c2*64); __syncthreads();
        loadB(g_Gs[2] + c2*8192); __syncthreads();
        mma_pass(0,c2*64); __syncthreads();
    }
    #pragma unroll
    for (int mt=0; mt<3; mt++) {
        int r0 = mt*16 + gid, r1 = r0 + 8;
        #pragma unroll
        for (int nt=0; nt<2; nt++) {
            int n0 = wrp*16 + nt*8 + 2*tq;
            if (r0 < 40) { s_t[r0*LDE + n0] = C[mt][nt][0]; s_t[r0*LDE + n0+1] = C[mt][nt][1]; }
            if (r1 < 40) { s_t[r1*LDE + n0] = C[mt][nt][2]; s_t[r1*LDE + n0+1] = C[mt][nt][3]; }
        }
    }
    __syncthreads();

    // ---------- Stage 4a: alpha/beta rank-1 terms ----------
    if (tid < 80) {
        int row = tid >> 1, sel = tid & 1;
        const float4* vec = (const float4*)(sel ? g_w : g_u);
        const float4* er  = (const float4*)(s_ef + row*LDE);
        float a = 0.f;
        #pragma unroll 8
        for (int i = 0; i < 32; i++) {
            float4 e = er[i], v = vec[i];
            a = fmaf(e.x,v.x,a); a = fmaf(e.y,v.y,a); a = fmaf(e.z,v.z,a); a = fmaf(e.w,v.w,a);
        }
        s_ab[sel*40 + row] = a;
    }
    __syncthreads();

    // ---------- Stage 4b: scores ----------
    if (tid < 200) {
        int s = tid/100, t2 = tid%100;
        int p0 = (t2/10)*2, r0 = (t2%10)*2;
        const u64t* qA = (const u64t*)(s_t  + (s*20 + p0)*LDE);
        const u64t* qB = (const u64t*)(s_t  + (s*20 + p0 + 1)*LDE);
        const u64t* kA = (const u64t*)(s_ef + (s*20 + r0)*LDE);
        const u64t* kB = (const u64t*)(s_ef + (s*20 + r0 + 1)*LDE);
        u64t a00=0ull, a01=0ull, a10=0ull, a11=0ull;
        #pragma unroll 8
        for (int i = 0; i < 64; i++) {
            u64t q0=qA[i], q1=qB[i], k0=kA[i], k1=kB[i];
            a00=ffma2(q0,k0,a00); a01=ffma2(q0,k1,a01);
            a10=ffma2(q1,k0,a10); a11=ffma2(q1,k1,a11);
        }
        float cc = g_c;
        float al0 = s_ab[s*20+p0] + cc, al1 = s_ab[s*20+p0+1] + cc;
        float be0 = s_ab[40+s*20+r0], be1 = s_ab[40+s*20+r0+1];
        float2 f;
        f=unpk(a00); s_sc[(s*20+p0  )*NP+r0  ] = f.x+f.y+al0+be0;
        f=unpk(a01); s_sc[(s*20+p0  )*NP+r0+1] = f.x+f.y+al0+be1;
        f=unpk(a10); s_sc[(s*20+p0+1)*NP+r0  ] = f.x+f.y+al1+be0;
        f=unpk(a11); s_sc[(s*20+p0+1)*NP+r0+1] = f.x+f.y+al1+be1;
    }
    __syncthreads();

    // ---------- Stage 5: softmax + column sums ----------
    if (tid < SPB*NP) {
        float* row = &s_sc[tid*NP];
        float mx = row[0];
        #pragma unroll
        for (int r=1;r<NP;r++) mx = fmaxf(mx, row[r]);
        float sum = 0.f;
        #pragma unroll
        for (int r=0;r<NP;r++){ float e=__expf(row[r]-mx); row[r]=e; sum+=e; }
        float inv = 1.f/sum;
        #pragma unroll
        for (int r=0;r<NP;r++) row[r] *= inv;
    }
    __syncthreads();
    if (tid < SPB*NP) {
        int s = tid/NP, r = tid - NP*s;
        float a = 0.f;
        #pragma unroll
        for (int p=0;p<NP;p++) a += s_sc[(s*NP+p)*NP + r];
        s_colw[tid] = a;
    }
    __syncthreads();

    // ---------- Stage 6: z = colw @ ef ----------
    {
        int s = tid >> 7, d = tid & 127;
        float a = 0.f;
        #pragma unroll
        for (int r=0;r<NP;r++) a = fmaf(s_colw[s*NP+r], s_ef[(s*NP+r)*LDE + d], a);
        s_z[s*128 + d] = a;
    }
    __syncthreads();

    // ---------- Stage 6b: pooled = z @ Wv + 20*bv ----------
    {
        int s = tid >> 7, d = tid & 127;
        float a = 20.f * bv[d];
        #pragma unroll 8
        for (int k=0;k<128;k++) a = fmaf(s_z[s*128+k], Wv[k*128+d], a);
        s_pool[s*128 + d] = a;
    }
    __syncthreads();

    // ---------- Stage 7: hr = relu(pooled @ Wr + br) ----------
    {
        float a0 = br[tid], a1 = a0;
        #pragma unroll 8
        for (int d=0;d<128;d++) {
            float w = Wr[d*256 + tid];
            a0 = fmaf(s_pool[d],     w, a0);
            a1 = fmaf(s_pool[128+d], w, a1);
        }
        s_hr[tid]     = fmaxf(a0, 0.f);
        s_hr[256+tid] = fmaxf(a1, 0.f);
    }
    __syncthreads();

    // ---------- Stage 8: heads ----------
    {
        int w = tid >> 5, ln = tid & 31;
        for (int o = w; o < 16; o += 8) {
            int s = o >> 3, head = (o >> 2) & 1, a = o & 3;
            const float* Wh = head ? Ws : Wm;
            float acc8 = 0.f;
            #pragma unroll
            for (int j = ln; j < 256; j += 32)
                acc8 = fmaf(s_hr[s*256 + j], Wh[j*4 + a], acc8);
            #pragma unroll
            for (int off = 16; off > 0; off >>= 1)
                acc8 += __shfl_xor_sync(0xffffffffu, acc8, off);
            if (ln == 0) {
                float val = acc8 + (head ? bs[a] : bm[a]);
                size_t bg = (size_t)(b0 + s);
                if (head) { val = fminf(fmaxf(val, -20.f), 2.f); out[(size_t)B*4 + bg*4 + a] = val; }
                else      { out[bg*4 + a] = val; }
            }
        }
    }
}

extern "C" void kernel_launch(void* const* d_in, const int* in_sizes, int n_in,
                              void* d_out, int out_size) {
    const float* obs = (const float*)d_in[0];
    const float* ag  = (const float*)d_in[1];
    const float* g   = (const float*)d_in[2];
    const float* W1  = (const float*)d_in[3];
    const float* b1  = (const float*)d_in[4];
    const float* W2  = (const float*)d_in[5];
    const float* b2  = (const float*)d_in[6];
    const float* Wq  = (const float*)d_in[7];
    const float* bq  = (const float*)d_in[8];
    const float* Wk  = (const float*)d_in[9];
    const float* bk  = (const float*)d_in[10];
    const float* Wv  = (const float*)d_in[11];
    const float* bv  = (const float*)d_in[12];
    const float* Wr  = (const float*)d_in[13];
    const float* br  = (const float*)d_in[14];
    const float* Wm  = (const float*)d_in[15];
    const float* bm  = (const float*)d_in[16];
    const float* Ws  = (const float*)d_in[17];
    const float* bs  = (const float*)d_in[18];
    const int* edges    = (const int*)d_in[19];
    const int* pred_ids = (const int*)d_in[20];
    float* out = (float*)d_out;

    const int B = in_sizes[0] / 85;

    setup_fold<<<128, 128>>>(Wq, Wk, bq, bk);
    setup_pack<<<256, 128>>>(W2);

    const size_t smem = (size_t)SMEM_ELEMS * 4;   // 104,400 B -> 2 blocks/SM
    cudaFuncSetAttribute(actor_kernel, cudaFuncAttributeMaxDynamicSharedMemorySize, (int)smem);

    actor_kernel<<<B / SPB, NT, smem>>>(
        obs, ag, g, W1, b1, b2, Wv, bv,
        Wr, br, Wm, bm, Ws, bs, edges, pred_ids, out, B);
}

// round 12
// speedup vs baseline: 1.4281x; 1.3984x over previous
#include <cuda_runtime.h>
#include <cuda_bf16.h>
#include <cstdint>

#define NT   256
#define SPB  2
#define NP   20
#define LDE  132
#define PA   136   // A smem pitch (bf16)
#define PB   72    // B smem pitch (bf16)
#define AHALF_BYTES 13056u   // 48*136*2
#define BHALF_BYTES 18432u   // 128*72*2

typedef unsigned long long u64t;

__device__ __forceinline__ u64t ffma2(u64t a, u64t b, u64t c) {
    u64t d; asm("fma.rn.f32x2 %0, %1, %2, %3;" : "=l"(d) : "l"(a), "l"(b), "l"(c)); return d;
}
__device__ __forceinline__ float2 unpk(u64t a) {
    float2 r; asm("mov.b64 {%0, %1}, %2;" : "=f"(r.x), "=f"(r.y) : "l"(a)); return r;
}
__device__ __forceinline__ uint32_t smem_u32(const void* p) {
    uint32_t a; asm("{ .reg .u64 t; cvta.to.shared.u64 t, %1; cvt.u32.u64 %0, t; }" : "=r"(a) : "l"(p)); return a;
}
#define LDSM4(r0,r1,r2,r3,a) asm volatile("ldmatrix.sync.aligned.m8n8.x4.shared.b16 {%0,%1,%2,%3},[%4];":"=r"(r0),"=r"(r1),"=r"(r2),"=r"(r3):"r"(a))
#define LDSM2(r0,r1,a)       asm volatile("ldmatrix.sync.aligned.m8n8.x2.shared.b16 {%0,%1},[%2];":"=r"(r0),"=r"(r1):"r"(a))
#define MMAB(Cr,A0,A1,A2,A3,B0,B1) asm volatile( \
    "mma.sync.aligned.m16n8k16.row.col.f32.bf16.bf16.f32 {%0,%1,%2,%3},{%4,%5,%6,%7},{%8,%9},{%0,%1,%2,%3};" \
    : "+f"(Cr[0]),"+f"(Cr[1]),"+f"(Cr[2]),"+f"(Cr[3]) \
    : "r"(A0),"r"(A1),"r"(A2),"r"(A3),"r"(B0),"r"(B1))

// ---- batch-invariant folded tables + pre-split weight images
__device__ float g_G[16384], g_u[128], g_w[128], g_c;
__device__ __align__(16) __nv_bfloat16 g_W2s[2][32768]; // [half][cc*8192 + n*64 + kk]
__device__ __align__(16) __nv_bfloat16 g_Gs[2][16384];  // [half][c2*8192 + n*64 + kk]

__global__ void setup_fold(const float* __restrict__ Wq, const float* __restrict__ Wk,
                           const float* __restrict__ bq, const float* __restrict__ bk)
{
    __shared__ float qa[128];
    const int a = blockIdx.x, t = threadIdx.x;
    qa[t] = Wq[a*128 + t];
    __syncthreads();
    const float scl = 0.088388347648318447f;
    const float* kb = Wk + t*128;
    float acc = 0.f;
    #pragma unroll 8
    for (int d = 0; d < 128; d++) acc = fmaf(qa[d], kb[d], acc);
    g_G[a*128 + t] = acc * scl;
    if (t == 0) { float u=0.f; for(int d=0;d<128;d++) u=fmaf(qa[d],bk[d],u); g_u[a]=u*scl; }
    if (a == 0) {
        float w=0.f; for(int d=0;d<128;d++) w=fmaf(kb[d],bq[d],w); g_w[t]=w*scl;
        if (t==0){ float c=0.f; for(int d=0;d<128;d++) c=fmaf(bq[d],bk[d],c); g_c=c*scl; }
    }
}

__global__ void setup_pack(const float* __restrict__ W2) {
    int idx = blockIdx.x*128 + threadIdx.x;   // 32768 threads
    {
        int k = idx >> 7, n = idx & 127;
        float v = W2[k*128 + n];
        int dst = ((k>>6)*128 + n)*64 + (k&63);
        __nv_bfloat16 h = __float2bfloat16(v); float r = v - __bfloat162float(h);
        g_W2s[0][dst]=h; g_W2s[1][dst]=__float2bfloat16(r);
    }
    if (idx < 16384) {
        int k = idx >> 7, n = idx & 127;
        float v = g_G[k*128 + n];
        int dst = ((k>>6)*128 + n)*64 + (k&63);
        __nv_bfloat16 h = __float2bfloat16(v); float r = v - __bfloat162float(h);
        g_Gs[0][dst]=h; g_Gs[1][dst]=__float2bfloat16(r);
    }
}

// smem float offsets
#define OFF_INP  0        // 800  [overlay: hr 512]
#define OFF_EF   800      // 5280 (40 x 132)
#define OFF_T    6080     // 5280
#define OFF_A    11360    // 6528 floats = 2 bf16 halves of A[48][136]
#define OFF_B    17888    // 9216 floats = 2 bf16 halves of B[128][72]  [overlay: sc/colw/ab/z/pool]
#define OFF_OBS  27104    // 176
#define OFF_DG   27280    // 64
#define OFF_INT  27344    // 100 ints
#define SMEM_ELEMS 27444
#define OFF_SC   OFF_B
#define OFF_COLW (OFF_B + 800)
#define OFF_AB   (OFF_B + 848)
#define OFF_Z    (OFF_B + 928)
#define OFF_POOL (OFF_B + 1184)
#define OFF_HR   0

__global__ __launch_bounds__(NT, 2)
void actor_kernel(
    const float* __restrict__ obs, const float* __restrict__ ag, const float* __restrict__ g,
    const float* __restrict__ W1, const float* __restrict__ b1, const float* __restrict__ b2,
    const float* __restrict__ Wv, const float* __restrict__ bv,
    const float* __restrict__ Wr, const float* __restrict__ br,
    const float* __restrict__ Wm, const float* __restrict__ bm,
    const float* __restrict__ Ws, const float* __restrict__ bs,
    const int* __restrict__ edges, const int* __restrict__ pred_ids,
    float* __restrict__ out, int B)
{
    extern __shared__ float sm[];
    float* s_inp  = sm + OFF_INP;
    float* s_ef   = sm + OFF_EF;
    float* s_t    = sm + OFF_T;
    __nv_bfloat16* s_Abf = (__nv_bfloat16*)(sm + OFF_A);   // halves at +0, +13056 bytes
    __nv_bfloat16* s_Bbf = (__nv_bfloat16*)(sm + OFF_B);   // halves at +0, +18432 bytes
    float* s_obs  = sm + OFF_OBS;
    float* s_dg   = sm + OFF_DG;
    float* s_sc   = sm + OFF_SC;
    float* s_colw = sm + OFF_COLW;
    float* s_ab   = sm + OFF_AB;
    float* s_z    = sm + OFF_Z;
    float* s_pool = sm + OFF_POOL;
    float* s_hr   = sm + OFF_HR;
    int*   s_edge = (int*)(sm + OFF_INT);
    int*   s_pred = s_edge + 40;

    const int tid = threadIdx.x;
    const int b0  = blockIdx.x * SPB;

    // ---------- Stage 0: inputs ----------
    for (int i = tid; i < SPB*85; i += NT) {
        int s = i/85, c = i-85*s;
        s_obs[s*88+c] = obs[(size_t)(b0+s)*85 + c];
    }
    for (int i = tid; i < SPB*30; i += NT) {
        int s = i/30, c = i-30*s;
        s_dg[s*32+c] = g[(size_t)(b0+s)*30 + c] - ag[(size_t)(b0+s)*30 + c];
    }
    if (tid < 40) s_edge[tid] = edges[tid];
    if (tid < 60) s_pred[tid] = pred_ids[tid];
    // zero A pad rows 40..47 (both halves)
    for (int i = tid; i < 2*8*PA; i += NT) {
        int h = i/(8*PA), rem = i%(8*PA);
        s_Abf[h*6528 + (40 + rem/PA)*PA + rem%PA] = __float2bfloat16(0.f);
    }
    __syncthreads();
    for (int i = tid; i < SPB*NP*19; i += NT) {
        int s = i/(NP*19); int rem = i - s*NP*19;
        int p = rem/19;    int c = rem - 19*p;
        float val;
        if (c < 10)      val = s_obs[s*88 + c];
        else if (c < 13) val = s_dg[s*32 + s_pred[p*3 + (c-10)]];
        else if (c < 16) val = s_obs[s*88 + 10 + s_edge[p*2]   * 15 + (c-13)];
        else             val = s_obs[s*88 + 10 + s_edge[p*2+1] * 15 + (c-16)];
        s_inp[(s*NP + p)*20 + c] = val;
    }
    for (int i = tid; i < SPB*NP; i += NT) s_inp[i*20 + 19] = 0.f;
    __syncthreads();

    // ---------- mma thread mapping ----------
    const int lane = tid & 31, wrp = tid >> 5;
    const int gid = lane >> 2, tq = lane & 3;
    const int arow  = (lane & 7) + 8*((lane >> 3) & 1);
    const int acolh = 8*(lane >> 4);
    const uint32_t aBase = smem_u32(s_Abf);
    const uint32_t bAddr0 = smem_u32(s_Bbf) + (uint32_t)(((wrp*16 + (lane & 7))*PB + 8*((lane >> 3) & 1))*2);

    float C[3][2][4];
    #pragma unroll
    for (int mt=0; mt<3; mt++) { C[mt][0][0]=C[mt][0][1]=C[mt][0][2]=C[mt][0][3]=0.f;
                                 C[mt][1][0]=C[mt][1][1]=C[mt][1][2]=C[mt][1][3]=0.f; }

    // load both B halves for a chunk (2 x 8192 bf16)
    auto loadB2 = [&](const __nv_bfloat16* srcH, const __nv_bfloat16* srcM) {
        const float4* sp0 = (const float4*)srcH;
        const float4* sp1 = (const float4*)srcM;
        #pragma unroll
        for (int j=0; j<4; j++) {
            int i = tid + j*256; int row = i>>3, seg = i&7;
            *(float4*)(s_Bbf + row*PB + seg*8)        = sp0[i];
            *(float4*)(s_Bbf + 9216 + row*PB + seg*8) = sp1[i];
        }
    };
    auto mma_pass = [&](int aHalf, int bHalf, int kof) {
        uint32_t ab = aBase + (uint32_t)aHalf*AHALF_BYTES;
        uint32_t bb = bAddr0 + (uint32_t)bHalf*BHALF_BYTES;
        #pragma unroll
        for (int ks2=0; ks2<4; ks2++) {
            int k0 = ks2*16;
            uint32_t b0a,b1a,b0b,b1b;
            LDSM2(b0a,b1a, bb + (uint32_t)(k0*2));
            LDSM2(b0b,b1b, bb + (uint32_t)((8*PB + k0)*2));
            #pragma unroll
            for (int mt=0; mt<3; mt++) {
                uint32_t aad = ab + (uint32_t)(((mt*16 + arow)*PA + kof + k0 + acolh)*2);
                uint32_t a0,a1,a2,a3; LDSM4(a0,a1,a2,a3,aad);
                MMAB(C[mt][0],a0,a1,a2,a3,b0a,b1a);
                MMAB(C[mt][1],a0,a1,a2,a3,b0b,b1b);
            }
        }
    };

    // ---------- Stage 1+2: ef = relu(relu(inp@W1+b1)@W2+b2), 3-pass double-split ----------
    for (int cc = 0; cc < 4; cc++) {
        {   // stage1: h chunk [40 rows][64 cols] -> split2 into A halves
            int hc = tid & 63, g4 = tid >> 6;
            int hcol = cc*64 + hc;
            float w1r[19];
            #pragma unroll
            for (int c=0;c<19;c++) w1r[c] = W1[c*256 + hcol];
            float bb = b1[hcol];
            #pragma unroll
            for (int r=0;r<10;r++) {
                int row = g4*10 + r;
                const float4* ip = (const float4*)(s_inp + row*20);
                float4 i0=ip[0], i1=ip[1], i2=ip[2], i3=ip[3], i4=ip[4];
                float a = bb;
                a=fmaf(i0.x,w1r[0],a);  a=fmaf(i0.y,w1r[1],a);  a=fmaf(i0.z,w1r[2],a);  a=fmaf(i0.w,w1r[3],a);
                a=fmaf(i1.x,w1r[4],a);  a=fmaf(i1.y,w1r[5],a);  a=fmaf(i1.z,w1r[6],a);  a=fmaf(i1.w,w1r[7],a);
                a=fmaf(i2.x,w1r[8],a);  a=fmaf(i2.y,w1r[9],a);  a=fmaf(i2.z,w1r[10],a); a=fmaf(i2.w,w1r[11],a);
                a=fmaf(i3.x,w1r[12],a); a=fmaf(i3.y,w1r[13],a); a=fmaf(i3.z,w1r[14],a); a=fmaf(i3.w,w1r[15],a);
                a=fmaf(i4.x,w1r[16],a); a=fmaf(i4.y,w1r[17],a); a=fmaf(i4.z,w1r[18],a);
                a = fmaxf(a, 0.f);
                __nv_bfloat16 h = __float2bfloat16(a); float r1 = a - __bfloat162float(h);
                int o = row*PA + hc;
                s_Abf[o] = h; s_Abf[6528+o] = __float2bfloat16(r1);
            }
        }
        loadB2(g_W2s[0] + cc*8192, g_W2s[1] + cc*8192);
        __syncthreads();
        mma_pass(0,0,0);   // hh
        mma_pass(1,0,0);   // lo_A * hi_B
        mma_pass(0,1,0);   // hi_A * lo_B
        __syncthreads();
    }
    // epilogue: bias+relu -> s_ef fp32 + split2 -> A halves (rows<40)
    #pragma unroll
    for (int mt=0; mt<3; mt++) {
        int r0 = mt*16 + gid, r1 = r0 + 8;
        #pragma unroll
        for (int nt=0; nt<2; nt++) {
            int n0 = wrp*16 + nt*8 + 2*tq;
            float bb0 = b2[n0], bb1 = b2[n0+1];
            float v[4] = { fmaxf(C[mt][nt][0]+bb0,0.f), fmaxf(C[mt][nt][1]+bb1,0.f),
                           fmaxf(C[mt][nt][2]+bb0,0.f), fmaxf(C[mt][nt][3]+bb1,0.f) };
            int rr[2] = { r0, r1 };
            #pragma unroll
            for (int q=0; q<4; q++) {
                int row = rr[q>>1], col = n0 + (q&1);
                if (row < 40) {
                    float a = v[q];
                    s_ef[row*LDE + col] = a;
                    __nv_bfloat16 h = __float2bfloat16(a); float r1f = a - __bfloat162float(h);
                    int o = row*PA + col;
                    s_Abf[o] = h; s_Abf[6528+o] = __float2bfloat16(r1f);
                }
            }
            C[mt][nt][0]=C[mt][nt][1]=C[mt][nt][2]=C[mt][nt][3]=0.f;  // re-zero for stage3
        }
    }
    __syncthreads();

    // ---------- Stage 3: t = ef @ G, 3-pass double-split ----------
    for (int c2 = 0; c2 < 2; c2++) {
        loadB2(g_Gs[0] + c2*8192, g_Gs[1] + c2*8192);
        __syncthreads();
        mma_pass(0,0,c2*64);
        mma_pass(1,0,c2*64);
        mma_pass(0,1,c2*64);
        __syncthreads();
    }
    #pragma unroll
    for (int mt=0; mt<3; mt++) {
        int r0 = mt*16 + gid, r1 = r0 + 8;
        #pragma unroll
        for (int nt=0; nt<2; nt++) {
            int n0 = wrp*16 + nt*8 + 2*tq;
            if (r0 < 40) { s_t[r0*LDE + n0] = C[mt][nt][0]; s_t[r0*LDE + n0+1] = C[mt][nt][1]; }
            if (r1 < 40) { s_t[r1*LDE + n0] = C[mt][nt][2]; s_t[r1*LDE + n0+1] = C[mt][nt][3]; }
        }
    }
    __syncthreads();

    // ---------- Stage 4a: alpha/beta rank-1 terms ----------
    if (tid < 80) {
        int row = tid >> 1, sel = tid & 1;
        const float4* vec = (const float4*)(sel ? g_w : g_u);
        const float4* er  = (const float4*)(s_ef + row*LDE);
        float a = 0.f;
        #pragma unroll 8
        for (int i = 0; i < 32; i++) {
            float4 e = er[i], v = vec[i];
            a = fmaf(e.x,v.x,a); a = fmaf(e.y,v.y,a); a = fmaf(e.z,v.z,a); a = fmaf(e.w,v.w,a);
        }
        s_ab[sel*40 + row] = a;
    }
    __syncthreads();

    // ---------- Stage 4b: scores ----------
    if (tid < 200) {
        int s = tid/100, t2 = tid%100;
        int p0 = (t2/10)*2, r0 = (t2%10)*2;
        const u64t* qA = (const u64t*)(s_t  + (s*20 + p0)*LDE);
        const u64t* qB = (const u64t*)(s_t  + (s*20 + p0 + 1)*LDE);
        const u64t* kA = (const u64t*)(s_ef + (s*20 + r0)*LDE);
        const u64t* kB = (const u64t*)(s_ef + (s*20 + r0 + 1)*LDE);
        u64t a00=0ull, a01=0ull, a10=0ull, a11=0ull;
        #pragma unroll 8
        for (int i = 0; i < 64; i++) {
            u64t q0=qA[i], q1=qB[i], k0=kA[i], k1=kB[i];
            a00=ffma2(q0,k0,a00); a01=ffma2(q0,k1,a01);
            a10=ffma2(q1,k0,a10); a11=ffma2(q1,k1,a11);
        }
        float cc = g_c;
        float al0 = s_ab[s*20+p0] + cc, al1 = s_ab[s*20+p0+1] + cc;
        float be0 = s_ab[40+s*20+r0], be1 = s_ab[40+s*20+r0+1];
        float2 f;
        f=unpk(a00); s_sc[(s*20+p0  )*NP+r0  ] = f.x+f.y+al0+be0;
        f=unpk(a01); s_sc[(s*20+p0  )*NP+r0+1] = f.x+f.y+al0+be1;
        f=unpk(a10); s_sc[(s*20+p0+1)*NP+r0  ] = f.x+f.y+al1+be0;
        f=unpk(a11); s_sc[(s*20+p0+1)*NP+r0+1] = f.x+f.y+al1+be1;
    }
    __syncthreads();

    // ---------- Stage 5: softmax + column sums ----------
    if (tid < SPB*NP) {
        float* row = &s_sc[tid*NP];
        float mx = row[0];
        #pragma unroll
        for (int r=1;r<NP;r++) mx = fmaxf(mx, row[r]);
        float sum = 0.f;
        #pragma unroll
        for (int r=0;r<NP;r++){ float e=__expf(row[r]-mx); row[r]=e; sum+=e; }
        float inv = 1.f/sum;
        #pragma unroll
        for (int r=0;r<NP;r++) row[r] *= inv;
    }
    __syncthreads();
    if (tid < SPB*NP) {
        int s = tid/NP, r = tid - NP*s;
        float a = 0.f;
        #pragma unroll
        for (int p=0;p<NP;p++) a += s_sc[(s*NP+p)*NP + r];
        s_colw[tid] = a;
    }
    __syncthreads();

    // ---------- Stage 6: z = colw @ ef ----------
    {
        int s = tid >> 7, d = tid & 127;
        float a = 0.f;
        #pragma unroll
        for (int r=0;r<NP;r++) a = fmaf(s_colw[s*NP+r], s_ef[(s*NP+r)*LDE + d], a);
        s_z[s*128 + d] = a;
    }
    __syncthreads();

    // ---------- Stage 6b: pooled = z @ Wv + 20*bv ----------
    {
        int s = tid >> 7, d = tid & 127;
        float a = 20.f * bv[d];
        #pragma unroll 8
        for (int k=0;k<128;k++) a = fmaf(s_z[s*128+k], Wv[k*128+d], a);
        s_pool[s*128 + d] = a;
    }
    __syncthreads();

    // ---------- Stage 7: hr = relu(pooled @ Wr + br) ----------
    {
        float a0 = br[tid], a1 = a0;
        #pragma unroll 8
        for (int d=0;d<128;d++) {
            float w = Wr[d*256 + tid];
            a0 = fmaf(s_pool[d],     w, a0);
            a1 = fmaf(s_pool[128+d], w, a1);
        }
        s_hr[tid]     = fmaxf(a0, 0.f);
        s_hr[256+tid] = fmaxf(a1, 0.f);
    }
    __syncthreads();

    // ---------- Stage 8: heads ----------
    {
        int w = tid >> 5, ln = tid & 31;
        for (int o = w; o < 16; o += 8) {
            int s = o >> 3, head = (o >> 2) & 1, a = o & 3;
            const float* Wh = head ? Ws : Wm;
            float acc8 = 0.f;
            #pragma unroll
            for (int j = ln; j < 256; j += 32)
                acc8 = fmaf(s_hr[s*256 + j], Wh[j*4 + a], acc8);
            #pragma unroll
            for (int off = 16; off > 0; off >>= 1)
                acc8 += __shfl_xor_sync(0xffffffffu, acc8, off);
            if (ln == 0) {
                float val = acc8 + (head ? bs[a] : bm[a]);
                size_t bg = (size_t)(b0 + s);
                if (head) { val = fminf(fmaxf(val, -20.f), 2.f); out[(size_t)B*4 + bg*4 + a] = val; }
                else      { out[bg*4 + a] = val; }
            }
        }
    }
}

extern "C" void kernel_launch(void* const* d_in, const int* in_sizes, int n_in,
                              void* d_out, int out_size) {
    const float* obs = (const float*)d_in[0];
    const float* ag  = (const float*)d_in[1];
    const float* g   = (const float*)d_in[2];
    const float* W1  = (const float*)d_in[3];
    const float* b1  = (const float*)d_in[4];
    const float* W2  = (const float*)d_in[5];
    const float* b2  = (const float*)d_in[6];
    const float* Wq  = (const float*)d_in[7];
    const float* bq  = (const float*)d_in[8];
    const float* Wk  = (const float*)d_in[9];
    const float* bk  = (const float*)d_in[10];
    const float* Wv  = (const float*)d_in[11];
    const float* bv  = (const float*)d_in[12];
    const float* Wr  = (const float*)d_in[13];
    const float* br  = (const float*)d_in[14];
    const float* Wm  = (const float*)d_in[15];
    const float* bm  = (const float*)d_in[16];
    const float* Ws  = (const float*)d_in[17];
    const float* bs  = (const float*)d_in[18];
    const int* edges    = (const int*)d_in[19];
    const int* pred_ids = (const int*)d_in[20];
    float* out = (float*)d_out;

    const int B = in_sizes[0] / 85;

    setup_fold<<<128, 128>>>(Wq, Wk, bq, bk);
    setup_pack<<<256, 128>>>(W2);

    const size_t smem = (size_t)SMEM_ELEMS * 4;   // 109,776 B -> 2 blocks/SM
    cudaFuncSetAttribute(actor_kernel, cudaFuncAttributeMaxDynamicSharedMemorySize, (int)smem);

    actor_kernel<<<B / SPB, NT, smem>>>(
        obs, ag, g, W1, b1, b2, Wv, bv,
        Wr, br, Wm, bm, Ws, bs, edges, pred_ids, out, B);
}